// round 2
// baseline (speedup 1.0000x reference)
#include <cuda_runtime.h>
#include <cuda_bf16.h>
#include <cstdint>

// ---------------------------------------------------------------------------
// ScaleCausalAttention  (B=64, N=341, D=768, H=12, hd=64)
//   qkv  = x @ qkv_w^T + qkv_b          [B,N,2304]
//   attn = softmax(q k^T * 0.125 + scale-causal mask) v   per head
//   out  = attn_out @ proj_w^T + proj_b [B,N,768]
//
// Mask structure: cum = [0,1,5,21,85,341]. Query q attends keys < limit(q):
//   q==0 -> 341 ; q in [1,5) -> 5 ; [5,21) -> 21 ; [21,85) -> 85 ; [85,341) -> 341
// ---------------------------------------------------------------------------

#define SEQ_N   341
#define DIM     768
#define DIM3    2304
#define HEADS   12
#define HEADDIM 64
#define BATCH   64
#define M_ROWS  (BATCH * SEQ_N)   // 21824

// Scratch (device globals: allocation-free per harness rules).
// Kernels reference these directly -- no cudaGetSymbolAddress in the
// capture path, keeping kernel_launch pure kernel launches.
__device__ float g_qkv[(size_t)M_ROWS * DIM3];   // ~201 MB
__device__ float g_att[(size_t)M_ROWS * DIM];    // ~67 MB

// ---------------------------------------------------------------------------
// SGEMM:  C[m,n] = sum_k A[m,k] * B[n,k] + bias[n]
// A: [M,K] row-major, B: [Nc,K] row-major (weights stored [out,in]),
// 128x128 tile, BK=16, 256 threads, 8x8 micro-tile per thread.
// A==nullptr -> read from g_att ; C==nullptr -> write to g_qkv.
// Nc and K are multiples of 128/16 for all our calls; M is guarded.
// ---------------------------------------------------------------------------
#define BM 128
#define BN 128
#define BK 16

__global__ __launch_bounds__(256, 2)
void sgemm_bias(const float* __restrict__ Ap, const float* __restrict__ B,
                const float* __restrict__ bias, float* __restrict__ Cp,
                int M, int Nc, int K)
{
    const float* A = Ap ? Ap : (const float*)g_att;
    float*       C = Cp ? Cp : (float*)g_qkv;

    __shared__ float As[BK][BM + 4];
    __shared__ float Bs[BK][BN + 4];

    const int tid = threadIdx.x;
    const int block_row = blockIdx.y * BM;
    const int block_col = blockIdx.x * BN;

    const int tr = (tid / 16) * 8;   // 0..120
    const int tc = (tid % 16) * 8;

    float acc[8][8];
#pragma unroll
    for (int i = 0; i < 8; i++)
#pragma unroll
        for (int j = 0; j < 8; j++) acc[i][j] = 0.f;

    // Each thread loads 2 float4 from A and 2 float4 from B per BK-slab.
    const int ld_row  = tid >> 2;          // 0..63
    const int ld_col4 = (tid & 3) * 4;     // 0,4,8,12

    for (int k0 = 0; k0 < K; k0 += BK) {
#pragma unroll
        for (int i = 0; i < 2; i++) {
            int r = ld_row + i * 64;
            int grow = block_row + r;
            float4 v;
            if (grow < M)
                v = *reinterpret_cast<const float4*>(A + (size_t)grow * K + k0 + ld_col4);
            else
                v = make_float4(0.f, 0.f, 0.f, 0.f);
            As[ld_col4 + 0][r] = v.x;
            As[ld_col4 + 1][r] = v.y;
            As[ld_col4 + 2][r] = v.z;
            As[ld_col4 + 3][r] = v.w;
        }
#pragma unroll
        for (int i = 0; i < 2; i++) {
            int r = ld_row + i * 64;
            int gcol = block_col + r;   // Nc multiple of 128: no guard
            float4 v = *reinterpret_cast<const float4*>(B + (size_t)gcol * K + k0 + ld_col4);
            Bs[ld_col4 + 0][r] = v.x;
            Bs[ld_col4 + 1][r] = v.y;
            Bs[ld_col4 + 2][r] = v.z;
            Bs[ld_col4 + 3][r] = v.w;
        }
        __syncthreads();

#pragma unroll
        for (int k = 0; k < BK; k++) {
            float ar[8], br[8];
#pragma unroll
            for (int i = 0; i < 8; i++) ar[i] = As[k][tr + i];
#pragma unroll
            for (int j = 0; j < 8; j++) br[j] = Bs[k][tc + j];
#pragma unroll
            for (int i = 0; i < 8; i++)
#pragma unroll
                for (int j = 0; j < 8; j++)
                    acc[i][j] = fmaf(ar[i], br[j], acc[i][j]);
        }
        __syncthreads();
    }

    // Epilogue: add bias, store (two float4 per row).
    float bv[8];
#pragma unroll
    for (int j = 0; j < 8; j++) bv[j] = bias[block_col + tc + j];

#pragma unroll
    for (int i = 0; i < 8; i++) {
        int grow = block_row + tr + i;
        if (grow < M) {
            float* cp = C + (size_t)grow * Nc + block_col + tc;
            float4 o0 = make_float4(acc[i][0] + bv[0], acc[i][1] + bv[1],
                                    acc[i][2] + bv[2], acc[i][3] + bv[3]);
            float4 o1 = make_float4(acc[i][4] + bv[4], acc[i][5] + bv[5],
                                    acc[i][6] + bv[6], acc[i][7] + bv[7]);
            *reinterpret_cast<float4*>(cp + 0) = o0;
            *reinterpret_cast<float4*>(cp + 4) = o1;
        }
    }
}

// ---------------------------------------------------------------------------
// Attention: one block per (head, batch). 352 threads; thread t = query t.
// Online softmax over keys, K/V staged in 32-key smem tiles.
// Reads q/k/v from g_qkv; writes [B,N,D]-layout attn output to g_att.
// ---------------------------------------------------------------------------
#define ATT_THREADS 352
#define KT 32

__global__ __launch_bounds__(ATT_THREADS, 1)
void attn_kernel()
{
    const float* __restrict__ qkv = (const float*)g_qkv;
    float* __restrict__ att = (float*)g_att;

    const int h = blockIdx.x;
    const int b = blockIdx.y;
    const int tid = threadIdx.x;
    const int q = tid;

    __shared__ float Ks[KT * HEADDIM];
    __shared__ float Vs[KT * HEADDIM];

    const size_t base = (size_t)b * SEQ_N * DIM3;
    const int hoff = h * HEADDIM;

    float qr[HEADDIM];
    float acc[HEADDIM];
    float mval = -1e30f, l = 0.f;

    int limit;
    if (q == 0)       limit = 341;
    else if (q < 5)   limit = 5;
    else if (q < 21)  limit = 21;
    else if (q < 85)  limit = 85;
    else              limit = 341;

    if (q < SEQ_N) {
        const float* qp = qkv + base + (size_t)q * DIM3 + hoff;
#pragma unroll
        for (int d = 0; d < HEADDIM; d++) {
            qr[d]  = qp[d] * 0.125f;   // hd^-0.5
            acc[d] = 0.f;
        }
    }

    for (int kt = 0; kt < SEQ_N; kt += KT) {
        const int nk = min(KT, SEQ_N - kt);

        // stage K and V tiles (coalesced: 64 contiguous floats per key)
        for (int i = tid; i < nk * HEADDIM; i += ATT_THREADS) {
            int kk = i >> 6, d = i & 63;
            size_t row = base + (size_t)(kt + kk) * DIM3;
            Ks[i] = qkv[row + DIM     + hoff + d];
            Vs[i] = qkv[row + 2 * DIM + hoff + d];
        }
        __syncthreads();

        if (q < SEQ_N && kt < limit) {
            const int ke = min(nk, limit - kt);
            for (int kk = 0; kk < ke; kk++) {
                const float* kp = &Ks[kk * HEADDIM];
                float s0 = 0.f, s1 = 0.f, s2 = 0.f, s3 = 0.f;
#pragma unroll
                for (int d = 0; d < HEADDIM; d += 4) {
                    s0 = fmaf(qr[d + 0], kp[d + 0], s0);
                    s1 = fmaf(qr[d + 1], kp[d + 1], s1);
                    s2 = fmaf(qr[d + 2], kp[d + 2], s2);
                    s3 = fmaf(qr[d + 3], kp[d + 3], s3);
                }
                float s = (s0 + s1) + (s2 + s3);
                const float* vp = &Vs[kk * HEADDIM];
                if (s > mval) {
                    float sf = __expf(mval - s);   // 0 on first key (mval=-1e30)
                    l = l * sf + 1.f;
#pragma unroll
                    for (int d = 0; d < HEADDIM; d++)
                        acc[d] = fmaf(acc[d], sf, vp[d]);
                    mval = s;
                } else {
                    float p = __expf(s - mval);
                    l += p;
#pragma unroll
                    for (int d = 0; d < HEADDIM; d++)
                        acc[d] = fmaf(p, vp[d], acc[d]);
                }
            }
        }
        __syncthreads();
    }

    if (q < SEQ_N) {
        float inv = 1.f / l;
        float* op = att + ((size_t)b * SEQ_N + q) * DIM + hoff;
#pragma unroll
        for (int d = 0; d < HEADDIM; d++) op[d] = acc[d] * inv;
    }
}

// ---------------------------------------------------------------------------
// Launch -- pure kernel launches, nothing else (graph-capture safe).
// ---------------------------------------------------------------------------
extern "C" void kernel_launch(void* const* d_in, const int* in_sizes, int n_in,
                              void* d_out, int out_size)
{
    const float* x      = (const float*)d_in[0];
    const float* qkv_w  = (const float*)d_in[1];
    const float* qkv_b  = (const float*)d_in[2];
    const float* proj_w = (const float*)d_in[3];
    const float* proj_b = (const float*)d_in[4];
    float* out = (float*)d_out;

    // 1) QKV GEMM: [21824,768] x [2304,768]^T -> g_qkv [21824,2304]
    {
        dim3 grid(DIM3 / BN, (M_ROWS + BM - 1) / BM);
        sgemm_bias<<<grid, 256>>>(x, qkv_w, qkv_b, /*C=*/nullptr,
                                  M_ROWS, DIM3, DIM);
    }

    // 2) Attention per (head, batch): g_qkv -> g_att
    {
        dim3 grid(HEADS, BATCH);
        attn_kernel<<<grid, ATT_THREADS>>>();
    }

    // 3) Output projection: g_att [21824,768] x [768,768]^T -> out
    {
        dim3 grid(DIM / BN, (M_ROWS + BM - 1) / BM);
        sgemm_bias<<<grid, 256>>>(/*A=*/nullptr, proj_w, proj_b, out,
                                  M_ROWS, DIM, DIM);
    }
}

// round 5
// speedup vs baseline: 1.8040x; 1.8040x over previous
#include <cuda_runtime.h>
#include <cuda_bf16.h>
#include <cstdint>

// ---------------------------------------------------------------------------
// ScaleCausalAttention  (B=64, N=341, D=768, H=12, hd=64)
//   qkv  = x @ qkv_w^T + qkv_b          [B,N,2304]
//   attn = softmax(q k^T * 0.125 + scale-causal mask) v   per head
//   out  = attn_out @ proj_w^T + proj_b [B,N,768]
//
// Mask: cum = [0,1,5,21,85,341]. Query q attends keys < limit(q):
//   q==0 -> 341 ; [1,5) -> 5 ; [5,21) -> 21 ; [21,85) -> 85 ; [85,341) -> 341
// ---------------------------------------------------------------------------

#define SEQ_N   341
#define DIM     768
#define DIM3    2304
#define HEADS   12
#define HEADDIM 64
#define BATCH   64
#define M_ROWS  (BATCH * SEQ_N)   // 21824

// Scratch (device globals: allocation-free per harness rules).
__device__ float g_qkv[(size_t)M_ROWS * DIM3];   // ~201 MB
__device__ float g_att[(size_t)M_ROWS * DIM];    // ~67 MB

// ---------------------------------------------------------------------------
// TF32 tensor-core GEMM:  C[m,n] = sum_k A[m,k] * B[n,k] + bias[n]
// A: [M,K] row-major, B: [Nc,K] row-major (weights are [out,in]).
// 128x128x16 block tile, 256 threads (8 warps, 2x4), 64x32 warp tile,
// mma.sync.m16n8k8 tf32, fp32 accumulate, double-buffered smem
// (one __syncthreads per BK-slab). cvt.rna.tf32 applied at smem store.
// A==nullptr -> read g_att ; C==nullptr -> write g_qkv.
// Nc, K multiples of 128/16 for all our calls; M guarded.
// ---------------------------------------------------------------------------
#define BM 128
#define BN 128
#define BK 16
#define SPITCH 20   // floats per smem row: conflict-free fragment loads

__device__ __forceinline__ float to_tf32(float x) {
    uint32_t u;
    asm("cvt.rna.tf32.f32 %0, %1;" : "=r"(u) : "f"(x));
    return __uint_as_float(u);
}

__device__ __forceinline__ void mma_tf32(float* c, const uint32_t* a, const uint32_t* b) {
    asm volatile(
        "mma.sync.aligned.m16n8k8.row.col.f32.tf32.tf32.f32 "
        "{%0,%1,%2,%3}, {%4,%5,%6,%7}, {%8,%9}, {%0,%1,%2,%3};"
        : "+f"(c[0]), "+f"(c[1]), "+f"(c[2]), "+f"(c[3])
        : "r"(a[0]), "r"(a[1]), "r"(a[2]), "r"(a[3]),
          "r"(b[0]), "r"(b[1]));
}

__global__ __launch_bounds__(256)
void gemm_tf32(const float* __restrict__ Ap, const float* __restrict__ B,
               const float* __restrict__ bias, float* __restrict__ Cp,
               int M, int Nc, int K)
{
    const float* A = Ap ? Ap : (const float*)g_att;
    float*       C = Cp ? Cp : (float*)g_qkv;

    __shared__ float As[2][BM * SPITCH];
    __shared__ float Bs[2][BN * SPITCH];

    const int tid  = threadIdx.x;
    const int lane = tid & 31;
    const int warp = tid >> 5;
    const int wm   = (warp & 1) * 64;    // warp row origin in tile
    const int wn   = (warp >> 1) * 32;   // warp col origin in tile
    const int grp  = lane >> 2;          // 0..7
    const int qid  = lane & 3;           // 0..3

    const int brow = blockIdx.y * BM;
    const int bcol = blockIdx.x * BN;

    // global->smem loader mapping: 2 float4 from A, 2 from B per thread
    const int ld_row = tid >> 2;          // 0..63
    const int ld_c4  = (tid & 3) * 4;     // 0,4,8,12

    float acc[4][4][4];
#pragma unroll
    for (int mt = 0; mt < 4; mt++)
#pragma unroll
        for (int nt = 0; nt < 4; nt++)
#pragma unroll
            for (int i = 0; i < 4; i++) acc[mt][nt][i] = 0.f;

    float4 pa[2], pb[2];

    auto loadg = [&](int k0) {
#pragma unroll
        for (int i = 0; i < 2; i++) {
            int r = ld_row + i * 64;
            int gr = brow + r;
            pa[i] = (gr < M)
                ? *reinterpret_cast<const float4*>(A + (size_t)gr * K + k0 + ld_c4)
                : make_float4(0.f, 0.f, 0.f, 0.f);
            pb[i] = *reinterpret_cast<const float4*>(B + (size_t)(bcol + r) * K + k0 + ld_c4);
        }
    };
    auto stores = [&](int buf) {
#pragma unroll
        for (int i = 0; i < 2; i++) {
            int r = ld_row + i * 64;
            float4 va = make_float4(to_tf32(pa[i].x), to_tf32(pa[i].y),
                                    to_tf32(pa[i].z), to_tf32(pa[i].w));
            float4 vb = make_float4(to_tf32(pb[i].x), to_tf32(pb[i].y),
                                    to_tf32(pb[i].z), to_tf32(pb[i].w));
            *reinterpret_cast<float4*>(&As[buf][r * SPITCH + ld_c4]) = va;
            *reinterpret_cast<float4*>(&Bs[buf][r * SPITCH + ld_c4]) = vb;
        }
    };

    loadg(0);
    stores(0);
    __syncthreads();

    int cur = 0;
    for (int k0 = 0; k0 < K; k0 += BK) {
        const bool more = (k0 + BK) < K;
        if (more) loadg(k0 + BK);

#pragma unroll
        for (int ks = 0; ks < 2; ks++) {
            const int kb = ks * 8;
            uint32_t af[4][4], bf[4][2];
#pragma unroll
            for (int mt = 0; mt < 4; mt++) {
                const float* ap = &As[cur][(wm + mt * 16 + grp) * SPITCH + kb + qid];
                af[mt][0] = __float_as_uint(ap[0]);
                af[mt][1] = __float_as_uint(ap[8 * SPITCH]);
                af[mt][2] = __float_as_uint(ap[4]);
                af[mt][3] = __float_as_uint(ap[8 * SPITCH + 4]);
            }
#pragma unroll
            for (int nt = 0; nt < 4; nt++) {
                const float* bp = &Bs[cur][(wn + nt * 8 + grp) * SPITCH + kb + qid];
                bf[nt][0] = __float_as_uint(bp[0]);
                bf[nt][1] = __float_as_uint(bp[4]);
            }
#pragma unroll
            for (int mt = 0; mt < 4; mt++)
#pragma unroll
                for (int nt = 0; nt < 4; nt++)
                    mma_tf32(acc[mt][nt], af[mt], bf[nt]);
        }

        if (more) {
            stores(cur ^ 1);    // write NEXT buffer; nobody reads it yet
            __syncthreads();    // publish next buffer (cur buffer untouched)
            cur ^= 1;
        }
    }

    // Epilogue: bias add + store (float2 per fragment row)
#pragma unroll
    for (int nt = 0; nt < 4; nt++) {
        const int col = bcol + wn + nt * 8 + qid * 2;
        const float b0 = bias[col];
        const float b1 = bias[col + 1];
#pragma unroll
        for (int mt = 0; mt < 4; mt++) {
            const int row0 = brow + wm + mt * 16 + grp;
            if (row0 < M) {
                float2 o = make_float2(acc[mt][nt][0] + b0, acc[mt][nt][1] + b1);
                *reinterpret_cast<float2*>(C + (size_t)row0 * Nc + col) = o;
            }
            const int row1 = row0 + 8;
            if (row1 < M) {
                float2 o = make_float2(acc[mt][nt][2] + b0, acc[mt][nt][3] + b1);
                *reinterpret_cast<float2*>(C + (size_t)row1 * Nc + col) = o;
            }
        }
    }
}

// ---------------------------------------------------------------------------
// Attention: one block per (head, batch). 352 threads; thread t = query t.
// Branchless online softmax, 8-key sub-tiles with deferred rescale:
// accumulator is rescaled once per 8 keys; the 8 exp() are batched in a
// separate pass so MUFU latency overlaps the FMA accumulate.
// ---------------------------------------------------------------------------
#define ATT_THREADS 352
#define KT 32

__global__ __launch_bounds__(ATT_THREADS)
void attn_kernel()
{
    const float* __restrict__ qkv = (const float*)g_qkv;
    float* __restrict__ att = (float*)g_att;

    const int h   = blockIdx.x;
    const int b   = blockIdx.y;
    const int tid = threadIdx.x;
    const int q   = tid;

    __shared__ float Ks[KT * HEADDIM];
    __shared__ float Vs[KT * HEADDIM];

    const size_t base = (size_t)b * SEQ_N * DIM3;
    const int hoff = h * HEADDIM;

    float qr[HEADDIM];
    float acc[HEADDIM];
    float mval = -1e30f, l = 0.f;

    int limit;
    if (q == 0)       limit = 341;
    else if (q < 5)   limit = 5;
    else if (q < 21)  limit = 21;
    else if (q < 85)  limit = 85;
    else              limit = 341;

    if (q < SEQ_N) {
        const float4* qp = reinterpret_cast<const float4*>(qkv + base + (size_t)q * DIM3 + hoff);
#pragma unroll
        for (int d4 = 0; d4 < HEADDIM / 4; d4++) {
            float4 v = qp[d4];
            qr[d4 * 4 + 0] = v.x * 0.125f;
            qr[d4 * 4 + 1] = v.y * 0.125f;
            qr[d4 * 4 + 2] = v.z * 0.125f;
            qr[d4 * 4 + 3] = v.w * 0.125f;
        }
#pragma unroll
        for (int d = 0; d < HEADDIM; d++) acc[d] = 0.f;
    }

    for (int kt = 0; kt < SEQ_N; kt += KT) {
        const int nk = min(KT, SEQ_N - kt);

        // stage K and V tiles (float4, coalesced)
        for (int i = tid; i < nk * (HEADDIM / 4); i += ATT_THREADS) {
            const int kk = i >> 4;
            const int d4 = (i & 15) * 4;
            const size_t row = base + (size_t)(kt + kk) * DIM3;
            *reinterpret_cast<float4*>(&Ks[kk * HEADDIM + d4]) =
                *reinterpret_cast<const float4*>(qkv + row + DIM + hoff + d4);
            *reinterpret_cast<float4*>(&Vs[kk * HEADDIM + d4]) =
                *reinterpret_cast<const float4*>(qkv + row + 2 * DIM + hoff + d4);
        }
        __syncthreads();

        if (q < SEQ_N && kt < limit) {
            const int ke = min(nk, limit - kt);   // keys in this tile
            for (int sub = 0; sub < ke; sub += 8) {
                const int n8 = min(8, ke - sub);
                float s[8];
                // pass 1: scores for up to 8 keys
                for (int j = 0; j < 8; j++) {
                    if (j < n8) {
                        const float4* kp = reinterpret_cast<const float4*>(&Ks[(sub + j) * HEADDIM]);
                        float s0 = 0.f, s1 = 0.f, s2 = 0.f, s3 = 0.f;
#pragma unroll
                        for (int d4 = 0; d4 < HEADDIM / 4; d4++) {
                            float4 kv = kp[d4];
                            s0 = fmaf(qr[d4 * 4 + 0], kv.x, s0);
                            s1 = fmaf(qr[d4 * 4 + 1], kv.y, s1);
                            s2 = fmaf(qr[d4 * 4 + 2], kv.z, s2);
                            s3 = fmaf(qr[d4 * 4 + 3], kv.w, s3);
                        }
                        s[j] = (s0 + s1) + (s2 + s3);
                    } else {
                        s[j] = -1e30f;
                    }
                }
                // sub-tile max, single deferred rescale
                float mt = s[0];
#pragma unroll
                for (int j = 1; j < 8; j++) mt = fmaxf(mt, s[j]);
                const float mnew = fmaxf(mval, mt);
                const float corr = __expf(mval - mnew);   // 0 on first sub-tile
                mval = mnew;
                l *= corr;
#pragma unroll
                for (int d = 0; d < HEADDIM; d++) acc[d] *= corr;

                // pass 2: batch the 8 exps (independent MUFU, overlaps FMAs below)
                float p[8];
#pragma unroll
                for (int j = 0; j < 8; j++) p[j] = __expf(s[j] - mnew);  // ~0 for padded j

                // pass 3: V accumulate
                for (int j = 0; j < 8; j++) {
                    if (j < n8) {
                        l += p[j];
                        const float4* vp = reinterpret_cast<const float4*>(&Vs[(sub + j) * HEADDIM]);
#pragma unroll
                        for (int d4 = 0; d4 < HEADDIM / 4; d4++) {
                            float4 vv = vp[d4];
                            acc[d4 * 4 + 0] = fmaf(p[j], vv.x, acc[d4 * 4 + 0]);
                            acc[d4 * 4 + 1] = fmaf(p[j], vv.y, acc[d4 * 4 + 1]);
                            acc[d4 * 4 + 2] = fmaf(p[j], vv.z, acc[d4 * 4 + 2]);
                            acc[d4 * 4 + 3] = fmaf(p[j], vv.w, acc[d4 * 4 + 3]);
                        }
                    }
                }
            }
        }
        __syncthreads();
    }

    if (q < SEQ_N) {
        const float inv = 1.f / l;
        float* op = att + ((size_t)b * SEQ_N + q) * DIM + hoff;
#pragma unroll
        for (int d4 = 0; d4 < HEADDIM / 4; d4++) {
            float4 o = make_float4(acc[d4 * 4 + 0] * inv, acc[d4 * 4 + 1] * inv,
                                   acc[d4 * 4 + 2] * inv, acc[d4 * 4 + 3] * inv);
            *reinterpret_cast<float4*>(op + d4 * 4) = o;
        }
    }
}

// ---------------------------------------------------------------------------
// Launch -- pure kernel launches (graph-capture safe).
// ---------------------------------------------------------------------------
extern "C" void kernel_launch(void* const* d_in, const int* in_sizes, int n_in,
                              void* d_out, int out_size)
{
    const float* x      = (const float*)d_in[0];
    const float* qkv_w  = (const float*)d_in[1];
    const float* qkv_b  = (const float*)d_in[2];
    const float* proj_w = (const float*)d_in[3];
    const float* proj_b = (const float*)d_in[4];
    float* out = (float*)d_out;

    // 1) QKV GEMM: [21824,768] x [2304,768]^T -> g_qkv [21824,2304]
    {
        dim3 grid(DIM3 / BN, (M_ROWS + BM - 1) / BM);
        gemm_tf32<<<grid, 256>>>(x, qkv_w, qkv_b, /*C=*/nullptr,
                                 M_ROWS, DIM3, DIM);
    }

    // 2) Attention per (head, batch): g_qkv -> g_att
    {
        dim3 grid(HEADS, BATCH);
        attn_kernel<<<grid, ATT_THREADS>>>();
    }

    // 3) Output projection: g_att [21824,768] x [768,768]^T -> out
    {
        dim3 grid(DIM / BN, (M_ROWS + BM - 1) / BM);
        gemm_tf32<<<grid, 256>>>(/*A=*/nullptr, proj_w, proj_b, out,
                                 M_ROWS, DIM, DIM);
    }
}

// round 6
// speedup vs baseline: 1.9229x; 1.0659x over previous
#include <cuda_runtime.h>
#include <cuda_bf16.h>
#include <cstdint>

// ---------------------------------------------------------------------------
// ScaleCausalAttention  (B=64, N=341, D=768, H=12, hd=64)
//   qkv  = x @ qkv_w^T + qkv_b          [B,N,2304]
//   attn = softmax(q k^T * 0.125 + scale-causal mask) v   per head
//   out  = attn_out @ proj_w^T + proj_b [B,N,768]
//
// Mask: cum = [0,1,5,21,85,341]. Query q attends keys < limit(q):
//   q==0 -> 341 ; [1,5) -> 5 ; [5,21) -> 21 ; [21,85) -> 85 ; [85,341) -> 341
// ---------------------------------------------------------------------------

#define SEQ_N   341
#define DIM     768
#define DIM3    2304
#define HEADS   12
#define HEADDIM 64
#define BATCH   64
#define M_ROWS  (BATCH * SEQ_N)   // 21824

__device__ float g_qkv[(size_t)M_ROWS * DIM3];   // ~201 MB
__device__ float g_att[(size_t)M_ROWS * DIM];    // ~67 MB

// ---------------------------------------------------------------------------
// TF32 tensor-core GEMM with ldmatrix fragment loads.
// 128x128x16 tile, 256 threads (8 warps 2x4), 64x32 warp tile,
// mma.sync.m16n8k8 tf32, double-buffered smem.
// SPITCH=20 floats: rows 16B-aligned, 8-row ldmatrix phase covers all 32
// banks exactly once (stride 20 -> banks 0,20,8,28,16,4,24,12) -- conflict-free.
// ---------------------------------------------------------------------------
#define BM 128
#define BN 128
#define BK 16
#define SPITCH 20

__device__ __forceinline__ float to_tf32(float x) {
    uint32_t u;
    asm("cvt.rna.tf32.f32 %0, %1;" : "=r"(u) : "f"(x));
    return __uint_as_float(u);
}

__device__ __forceinline__ uint32_t smem_u32(const void* p) {
    return (uint32_t)__cvta_generic_to_shared(p);
}

__device__ __forceinline__ void ldsm_x4(uint32_t addr, uint32_t& r0, uint32_t& r1,
                                        uint32_t& r2, uint32_t& r3) {
    asm volatile("ldmatrix.sync.aligned.m8n8.x4.shared.b16 {%0,%1,%2,%3}, [%4];"
                 : "=r"(r0), "=r"(r1), "=r"(r2), "=r"(r3) : "r"(addr));
}

__device__ __forceinline__ void mma_tf32(float* c, const uint32_t* a, const uint32_t* b) {
    asm volatile(
        "mma.sync.aligned.m16n8k8.row.col.f32.tf32.tf32.f32 "
        "{%0,%1,%2,%3}, {%4,%5,%6,%7}, {%8,%9}, {%0,%1,%2,%3};"
        : "+f"(c[0]), "+f"(c[1]), "+f"(c[2]), "+f"(c[3])
        : "r"(a[0]), "r"(a[1]), "r"(a[2]), "r"(a[3]),
          "r"(b[0]), "r"(b[1]));
}

__global__ __launch_bounds__(256)
void gemm_tf32(const float* __restrict__ Ap, const float* __restrict__ B,
               const float* __restrict__ bias, float* __restrict__ Cp,
               int M, int Nc, int K)
{
    const float* A = Ap ? Ap : (const float*)g_att;
    float*       C = Cp ? Cp : (float*)g_qkv;

    __shared__ float As[2][BM * SPITCH];
    __shared__ float Bs[2][BN * SPITCH];

    const int tid  = threadIdx.x;
    const int lane = tid & 31;
    const int warp = tid >> 5;
    const int wm   = (warp & 1) * 64;
    const int wn   = (warp >> 1) * 32;
    const int grp  = lane >> 2;
    const int qid  = lane & 3;

    // ldmatrix per-lane address components
    const int lrow = lane & 15;           // row within 16-row group
    const int lksel = (lane >> 4) * 4;    // k-offset 0 or 4 (matrices 2,3)

    const int brow = blockIdx.y * BM;
    const int bcol = blockIdx.x * BN;

    const int ld_row = tid >> 2;
    const int ld_c4  = (tid & 3) * 4;

    float acc[4][4][4];
#pragma unroll
    for (int mt = 0; mt < 4; mt++)
#pragma unroll
        for (int nt = 0; nt < 4; nt++)
#pragma unroll
            for (int i = 0; i < 4; i++) acc[mt][nt][i] = 0.f;

    float4 pa[2], pb[2];

    auto loadg = [&](int k0) {
#pragma unroll
        for (int i = 0; i < 2; i++) {
            int r = ld_row + i * 64;
            int gr = brow + r;
            pa[i] = (gr < M)
                ? *reinterpret_cast<const float4*>(A + (size_t)gr * K + k0 + ld_c4)
                : make_float4(0.f, 0.f, 0.f, 0.f);
            pb[i] = *reinterpret_cast<const float4*>(B + (size_t)(bcol + r) * K + k0 + ld_c4);
        }
    };
    auto stores = [&](int buf) {
#pragma unroll
        for (int i = 0; i < 2; i++) {
            int r = ld_row + i * 64;
            float4 va = make_float4(to_tf32(pa[i].x), to_tf32(pa[i].y),
                                    to_tf32(pa[i].z), to_tf32(pa[i].w));
            float4 vb = make_float4(to_tf32(pb[i].x), to_tf32(pb[i].y),
                                    to_tf32(pb[i].z), to_tf32(pb[i].w));
            *reinterpret_cast<float4*>(&As[buf][r * SPITCH + ld_c4]) = va;
            *reinterpret_cast<float4*>(&Bs[buf][r * SPITCH + ld_c4]) = vb;
        }
    };

    loadg(0);
    stores(0);
    __syncthreads();

    int cur = 0;
    for (int k0 = 0; k0 < K; k0 += BK) {
        const bool more = (k0 + BK) < K;
        if (more) loadg(k0 + BK);

#pragma unroll
        for (int ks = 0; ks < 2; ks++) {
            const int kb = ks * 8;
            uint32_t af[4][4], bf[4][2];
            // A fragments: one ldmatrix.x4 per 16-row m-tile
#pragma unroll
            for (int mt = 0; mt < 4; mt++) {
                uint32_t a = smem_u32(&As[cur][(wm + mt * 16 + lrow) * SPITCH + kb + lksel]);
                ldsm_x4(a, af[mt][0], af[mt][1], af[mt][2], af[mt][3]);
            }
            // B fragments: one ldmatrix.x4 per PAIR of 8-row n-tiles
#pragma unroll
            for (int p = 0; p < 2; p++) {
                uint32_t a = smem_u32(&Bs[cur][(wn + p * 16 + lrow) * SPITCH + kb + lksel]);
                uint32_t r0, r1, r2, r3;
                ldsm_x4(a, r0, r1, r2, r3);
                bf[2 * p][0]     = r0;  // b0 of nt=2p
                bf[2 * p + 1][0] = r1;  // b0 of nt=2p+1
                bf[2 * p][1]     = r2;  // b1 of nt=2p
                bf[2 * p + 1][1] = r3;  // b1 of nt=2p+1
            }
#pragma unroll
            for (int mt = 0; mt < 4; mt++)
#pragma unroll
                for (int nt = 0; nt < 4; nt++)
                    mma_tf32(acc[mt][nt], af[mt], bf[nt]);
        }

        if (more) {
            stores(cur ^ 1);
            __syncthreads();
            cur ^= 1;
        }
    }

    // Epilogue
#pragma unroll
    for (int nt = 0; nt < 4; nt++) {
        const int col = bcol + wn + nt * 8 + qid * 2;
        const float b0 = bias[col];
        const float b1 = bias[col + 1];
#pragma unroll
        for (int mt = 0; mt < 4; mt++) {
            const int row0 = brow + wm + mt * 16 + grp;
            if (row0 < M) {
                float2 o = make_float2(acc[mt][nt][0] + b0, acc[mt][nt][1] + b1);
                *reinterpret_cast<float2*>(C + (size_t)row0 * Nc + col) = o;
            }
            const int row1 = row0 + 8;
            if (row1 < M) {
                float2 o = make_float2(acc[mt][nt][2] + b0, acc[mt][nt][3] + b1);
                *reinterpret_cast<float2*>(C + (size_t)row1 * Nc + col) = o;
            }
        }
    }
}

// ---------------------------------------------------------------------------
// Attention: 2 threads per query (head-dim halves). Block = 256 threads
// covers 128 queries for one (b,h); grid (3, H, B). Online softmax with
// 8-key sub-tiles and deferred rescale; score = 32-dim dot + pair shfl.
// K/V smem layout half-interleaved: key*64 + inner*8 + half*4 so the two
// half-reads per warp hit disjoint bank groups (1 wavefront).
// ---------------------------------------------------------------------------
#define AQ     128
#define ATT_T  256
#define KT     32

__global__ __launch_bounds__(ATT_T, 2)
void attn_kernel()
{
    const float* __restrict__ qkv = (const float*)g_qkv;
    float* __restrict__ att = (float*)g_att;

    const int qc  = blockIdx.x;   // 0..2
    const int h   = blockIdx.y;
    const int b   = blockIdx.z;
    const int tid = threadIdx.x;
    const int q    = qc * AQ + (tid >> 1);
    const int half = tid & 1;
    const unsigned pairmask = 3u << (tid & 30 & 31);

    __shared__ float Ks[KT * HEADDIM];
    __shared__ float Vs[KT * HEADDIM];

    const size_t base = (size_t)b * SEQ_N * DIM3;
    const int hbase = h * HEADDIM;
    const int hoff  = hbase + half * 32;

    float qr[32], acc[32];
    float mval = -1e30f, l = 0.f;

    int limit;
    if (q == 0)       limit = 341;
    else if (q < 5)   limit = 5;
    else if (q < 21)  limit = 21;
    else if (q < 85)  limit = 85;
    else              limit = 341;

    const bool active = (q < SEQ_N);
    if (active) {
        const float4* qp = reinterpret_cast<const float4*>(qkv + base + (size_t)q * DIM3 + hoff);
#pragma unroll
        for (int d4 = 0; d4 < 8; d4++) {
            float4 v = qp[d4];
            qr[d4 * 4 + 0] = v.x * 0.125f;
            qr[d4 * 4 + 1] = v.y * 0.125f;
            qr[d4 * 4 + 2] = v.z * 0.125f;
            qr[d4 * 4 + 3] = v.w * 0.125f;
        }
#pragma unroll
        for (int d = 0; d < 32; d++) acc[d] = 0.f;
    }

    for (int kt = 0; kt < SEQ_N; kt += KT) {
        const int nk = min(KT, SEQ_N - kt);

        // stage K/V: global d4 chunk -> half-interleaved smem slot
        for (int i = tid; i < nk * 16; i += ATT_T) {
            const int kk = i >> 4;
            const int d4 = i & 15;            // 0..15 over full head dim
            const int ho = d4 >> 3;           // which half
            const int in = d4 & 7;            // inner chunk
            const int soff = kk * 64 + in * 8 + ho * 4;
            const size_t row = base + (size_t)(kt + kk) * DIM3;
            *reinterpret_cast<float4*>(&Ks[soff]) =
                *reinterpret_cast<const float4*>(qkv + row + DIM + hbase + d4 * 4);
            *reinterpret_cast<float4*>(&Vs[soff]) =
                *reinterpret_cast<const float4*>(qkv + row + 2 * DIM + hbase + d4 * 4);
        }
        __syncthreads();

        if (active && kt < limit) {
            const int ke = min(nk, limit - kt);
            for (int sub = 0; sub < ke; sub += 8) {
                const int n8 = min(8, ke - sub);
                float s[8];
                for (int j = 0; j < 8; j++) {
                    if (j < n8) {
                        const float* kp = &Ks[(sub + j) * 64 + half * 4];
                        float s0 = 0.f, s1 = 0.f, s2 = 0.f, s3 = 0.f;
#pragma unroll
                        for (int in = 0; in < 8; in++) {
                            float4 kv = *reinterpret_cast<const float4*>(kp + in * 8);
                            s0 = fmaf(qr[in * 4 + 0], kv.x, s0);
                            s1 = fmaf(qr[in * 4 + 1], kv.y, s1);
                            s2 = fmaf(qr[in * 4 + 2], kv.z, s2);
                            s3 = fmaf(qr[in * 4 + 3], kv.w, s3);
                        }
                        float sh = (s0 + s1) + (s2 + s3);
                        s[j] = sh + __shfl_xor_sync(pairmask, sh, 1);
                    } else {
                        s[j] = -1e30f;
                    }
                }
                float mt = s[0];
#pragma unroll
                for (int j = 1; j < 8; j++) mt = fmaxf(mt, s[j]);
                const float mnew = fmaxf(mval, mt);
                const float corr = __expf(mval - mnew);
                mval = mnew;
                l *= corr;
#pragma unroll
                for (int d = 0; d < 32; d++) acc[d] *= corr;

                float p[8];
#pragma unroll
                for (int j = 0; j < 8; j++) p[j] = __expf(s[j] - mnew);

                for (int j = 0; j < 8; j++) {
                    if (j < n8) {
                        l += p[j];
                        const float* vp = &Vs[(sub + j) * 64 + half * 4];
#pragma unroll
                        for (int in = 0; in < 8; in++) {
                            float4 vv = *reinterpret_cast<const float4*>(vp + in * 8);
                            acc[in * 4 + 0] = fmaf(p[j], vv.x, acc[in * 4 + 0]);
                            acc[in * 4 + 1] = fmaf(p[j], vv.y, acc[in * 4 + 1]);
                            acc[in * 4 + 2] = fmaf(p[j], vv.z, acc[in * 4 + 2]);
                            acc[in * 4 + 3] = fmaf(p[j], vv.w, acc[in * 4 + 3]);
                        }
                    }
                }
            }
        }
        __syncthreads();
    }

    if (active) {
        const float inv = 1.f / l;
        float* op = att + ((size_t)b * SEQ_N + q) * DIM + hoff;
#pragma unroll
        for (int d4 = 0; d4 < 8; d4++) {
            float4 o = make_float4(acc[d4 * 4 + 0] * inv, acc[d4 * 4 + 1] * inv,
                                   acc[d4 * 4 + 2] * inv, acc[d4 * 4 + 3] * inv);
            *reinterpret_cast<float4*>(op + d4 * 4) = o;
        }
    }
}

// ---------------------------------------------------------------------------
// Launch -- pure kernel launches (graph-capture safe).
// ---------------------------------------------------------------------------
extern "C" void kernel_launch(void* const* d_in, const int* in_sizes, int n_in,
                              void* d_out, int out_size)
{
    const float* x      = (const float*)d_in[0];
    const float* qkv_w  = (const float*)d_in[1];
    const float* qkv_b  = (const float*)d_in[2];
    const float* proj_w = (const float*)d_in[3];
    const float* proj_b = (const float*)d_in[4];
    float* out = (float*)d_out;

    // 1) QKV GEMM
    {
        dim3 grid(DIM3 / BN, (M_ROWS + BM - 1) / BM);
        gemm_tf32<<<grid, 256>>>(x, qkv_w, qkv_b, /*C=*/nullptr,
                                 M_ROWS, DIM3, DIM);
    }
    // 2) Attention
    {
        dim3 grid(3, HEADS, BATCH);
        attn_kernel<<<grid, ATT_T>>>();
    }
    // 3) Output projection
    {
        dim3 grid(DIM / BN, (M_ROWS + BM - 1) / BM);
        gemm_tf32<<<grid, 256>>>(/*A=*/nullptr, proj_w, proj_b, out,
                                 M_ROWS, DIM, DIM);
    }
}